// round 2
// baseline (speedup 1.0000x reference)
#include <cuda_runtime.h>
#include <cuda_bf16.h>

// Sinkhorn over [256, 512, 512], 10 iterations, T=1.
//
// Identity: the log-space Sinkhorn iterate is always la0[i,j] + u_i + v_j, so
// the recursion collapses to diagonal scaling on K = exp(la0):
//     r = 1/(K c),  c = 1/(K^T r)   (10 times, c starts at 1)
//     out[i,j] = exp(la0[i,j]) * r_i * c_j
// K is cached in bf16 scratch (rounding averages out across the 512-term
// sums: ~1e-4 relative on r,c). The output path uses the original fp32 la.
//
// One CTA per batch, forced to 1 CTA/SM via a dynamic-smem occupancy limiter
// so each wave's 148 tiles (74 MB) stay L2-resident across all 20 passes.

#define BATCH 256
#define N     512
#define NITER 10
#define TPB   512
#define NWARP (TPB / 32)
#define DYN_SMEM (130 * 1024)   // occupancy limiter: 1 CTA/SM -> L2-resident tiles

// 128 MB bf16 scratch for K (static __device__ array: no runtime allocation).
__device__ __nv_bfloat16 g_K[(size_t)BATCH * N * N];

// bf16x2 packed in a u32 -> two fp32, one ALU op each (no cvt sequence).
__device__ __forceinline__ float bf_lo(unsigned v) { return __uint_as_float(v << 16); }
__device__ __forceinline__ float bf_hi(unsigned v) { return __uint_as_float(v & 0xffff0000u); }

__global__ __launch_bounds__(TPB, 1)
void sinkhorn_kernel(const float* __restrict__ la, float* __restrict__ out) {
    __shared__ float r_s[N];
    __shared__ float c_s[N];
    __shared__ float part[4][N];   // col-pass partial sums (4 row-groups)

    const int tid  = threadIdx.x;
    const int warp = tid >> 5;
    const int lane = tid & 31;
    const size_t base = (size_t)blockIdx.x * (size_t)(N * N);

    const float*   la_b = la + base;
    __nv_bfloat16* K_b  = g_K + base;

    // ---- Phase 1: K = bf16(exp(la)), streamed with deep MLP ----
    const float4* la4 = (const float4*)la_b;
    uint2*        K8  = (uint2*)K_b;          // 4 bf16 per store
    #pragma unroll 8
    for (int idx = tid; idx < (N * N) / 4; idx += TPB) {
        float4 v = la4[idx];
        __nv_bfloat162 p0 = __floats2bfloat162_rn(__expf(v.x), __expf(v.y));
        __nv_bfloat162 p1 = __floats2bfloat162_rn(__expf(v.z), __expf(v.w));
        uint2 d;
        d.x = *reinterpret_cast<unsigned*>(&p0);
        d.y = *reinterpret_cast<unsigned*>(&p1);
        K8[idx] = d;
    }
    if (tid < N) c_s[tid] = 1.0f;
    __syncthreads();

    // ---- Phase 2: 10 iterations, r/c resident in smem ----
    for (int t = 0; t < NITER; t++) {
        // Row pass: r_i = 1 / sum_j K[i,j]*c[j].  Warp per row, uint4 (8 bf16)
        // per lane, 2 loads cover the 512 columns.
        for (int i = warp; i < N; i += NWARP) {
            const uint4* Krow = (const uint4*)(K_b + (size_t)i * N);
            float acc = 0.f;
            #pragma unroll
            for (int k = 0; k < 2; k++) {
                int v = k * 32 + lane;            // uint4 index; elems 8v..8v+7
                uint4 d = Krow[v];
                float4 c0 = *(const float4*)(c_s + 8 * v);
                float4 c1 = *(const float4*)(c_s + 8 * v + 4);
                acc += bf_lo(d.x) * c0.x + bf_hi(d.x) * c0.y
                     + bf_lo(d.y) * c0.z + bf_hi(d.y) * c0.w
                     + bf_lo(d.z) * c1.x + bf_hi(d.z) * c1.y
                     + bf_lo(d.w) * c1.z + bf_hi(d.w) * c1.w;
            }
            #pragma unroll
            for (int off = 16; off > 0; off >>= 1)
                acc += __shfl_xor_sync(0xffffffffu, acc, off);
            if (lane == 0) r_s[i] = __frcp_rn(acc);
        }
        __syncthreads();

        // Col pass: c_j = 1 / sum_i K[i,j]*r[i].  Thread owns 4 adjacent
        // columns (one uint2 per row), 4 row-groups of 128 threads each,
        // partials combined through smem. Fully coalesced (256 B/warp/req).
        {
            const int g = tid >> 7;          // row group 0..3
            const int u = tid & 127;         // column group: cols 4u..4u+3
            const __nv_bfloat16* Kp = K_b + (size_t)(g * 128) * N + 4 * u;
            float4 acc = make_float4(0.f, 0.f, 0.f, 0.f);
            #pragma unroll 8
            for (int ii = 0; ii < 128; ii++) {
                uint2 d = *(const uint2*)(Kp + (size_t)ii * N);
                float ri = r_s[g * 128 + ii];
                acc.x += bf_lo(d.x) * ri;
                acc.y += bf_hi(d.x) * ri;
                acc.z += bf_lo(d.y) * ri;
                acc.w += bf_hi(d.y) * ri;
            }
            *(float4*)(&part[g][4 * u]) = acc;
        }
        __syncthreads();
        c_s[tid] = __frcp_rn(part[0][tid] + part[1][tid] + part[2][tid] + part[3][tid]);
        __syncthreads();
    }

    // ---- Phase 3: out = exp(la) * r_i * c_j (fp32 path; bf16 never touches
    //      the output values directly) ----
    float4* out4 = (float4*)(out + base);
    #pragma unroll 8
    for (int idx = tid; idx < (N * N) / 4; idx += TPB) {
        float4 v = la4[idx];
        int e = idx * 4;
        int i = e >> 9;                      // N = 512
        int j = e & (N - 1);
        float  ri = r_s[i];
        float4 cj = *(const float4*)(c_s + j);
        float4 o;
        o.x = __expf(v.x) * ri * cj.x;
        o.y = __expf(v.y) * ri * cj.y;
        o.z = __expf(v.z) * ri * cj.z;
        o.w = __expf(v.w) * ri * cj.w;
        out4[idx] = o;
    }
}

extern "C" void kernel_launch(void* const* d_in, const int* in_sizes, int n_in,
                              void* d_out, int out_size) {
    const float* la  = (const float*)d_in[0];
    float*       out = (float*)d_out;
    // Non-stream call, legal during graph capture; enables >48KB dynamic smem.
    cudaFuncSetAttribute(sinkhorn_kernel,
                         cudaFuncAttributeMaxDynamicSharedMemorySize, DYN_SMEM);
    sinkhorn_kernel<<<BATCH, TPB, DYN_SMEM>>>(la, out);
}

// round 10
// speedup vs baseline: 1.5835x; 1.5835x over previous
#include <cuda_runtime.h>
#include <cuda_bf16.h>

// Sinkhorn over [256, 512, 512], 10 iterations, T=1.
//
// Identity: the log-space Sinkhorn iterate is always la0[i,j] + u_i + v_j, so
// the recursion collapses to diagonal scaling on K = exp(la0):
//     r = 1/(K c),  c = 1/(K^T r)   (10 times, c starts at 1)
//     out[i,j] = exp(la0[i,j]) * r_i * c_j
//
// ONE pass over K per iteration: warp-per-row computes the row dot -> r_i
// (butterfly reduce, all lanes get it), then immediately accumulates
// r_i*K[i,j] into per-lane register column accumulators (each lane owns 16
// fixed columns). Warp partials combine via smem. Iteration 0 is fused with
// K construction (c == 1). K lives in bf16 scratch; the output path uses the
// original fp32 la.

#define BATCH 256
#define N     512
#define NITER 10
#define TPB   512
#define NWARP (TPB / 32)
#define ROWS_PER_WARP (N / NWARP)      // 32
#define DYN_SMEM (92 * 1024)           // occupancy limiter: 1 CTA/SM (L2-resident K)

// 128 MB bf16 scratch for K (static __device__ array: no runtime allocation).
__device__ __nv_bfloat16 g_K[(size_t)BATCH * N * N];

// bf16x2 packed in a u32 -> two fp32, one ALU op each.
__device__ __forceinline__ float bf_lo(unsigned v) { return __uint_as_float(v << 16); }
__device__ __forceinline__ float bf_hi(unsigned v) { return __uint_as_float(v & 0xffff0000u); }

__device__ __forceinline__ unsigned pack_bf2(float lo, float hi) {
    __nv_bfloat162 p = __floats2bfloat162_rn(lo, hi);
    return *reinterpret_cast<unsigned*>(&p);
}

__device__ __forceinline__ void cvt8(uint4 d, float* f) {
    f[0] = bf_lo(d.x); f[1] = bf_hi(d.x);
    f[2] = bf_lo(d.y); f[3] = bf_hi(d.y);
    f[4] = bf_lo(d.z); f[5] = bf_hi(d.z);
    f[6] = bf_lo(d.w); f[7] = bf_hi(d.w);
}

__global__ __launch_bounds__(TPB, 1)
void sinkhorn_kernel(const float* __restrict__ la, float* __restrict__ out) {
    __shared__ float r_s[N];
    __shared__ float c_s[N];
    __shared__ float part[NWARP][N];   // per-warp column partials (32 KB)

    const int tid  = threadIdx.x;
    const int warp = tid >> 5;
    const int lane = tid & 31;
    const size_t base = (size_t)blockIdx.x * (size_t)(N * N);

    const float*   la_b = la + base;
    __nv_bfloat16* K_b  = g_K + base;

    // ================= Iteration 0, fused with K construction (c == 1) ======
    {
        float colacc[16];
        #pragma unroll
        for (int m = 0; m < 16; m++) colacc[m] = 0.f;

        for (int ri = 0; ri < ROWS_PER_WARP; ri++) {
            const int i = warp + ri * NWARP;
            const float4* lar = (const float4*)(la_b + (size_t)i * N);
            // lane's columns: j = 8*lane..8*lane+7  and  256+8*lane..+7
            float4 a0 = lar[2 * lane];
            float4 a1 = lar[2 * lane + 1];
            float4 b0 = lar[64 + 2 * lane];
            float4 b1 = lar[64 + 2 * lane + 1];
            float f[16];
            f[0]  = __expf(a0.x); f[1]  = __expf(a0.y);
            f[2]  = __expf(a0.z); f[3]  = __expf(a0.w);
            f[4]  = __expf(a1.x); f[5]  = __expf(a1.y);
            f[6]  = __expf(a1.z); f[7]  = __expf(a1.w);
            f[8]  = __expf(b0.x); f[9]  = __expf(b0.y);
            f[10] = __expf(b0.z); f[11] = __expf(b0.w);
            f[12] = __expf(b1.x); f[13] = __expf(b1.y);
            f[14] = __expf(b1.z); f[15] = __expf(b1.w);

            uint4 d0, d1;
            d0.x = pack_bf2(f[0],  f[1]);  d0.y = pack_bf2(f[2],  f[3]);
            d0.z = pack_bf2(f[4],  f[5]);  d0.w = pack_bf2(f[6],  f[7]);
            d1.x = pack_bf2(f[8],  f[9]);  d1.y = pack_bf2(f[10], f[11]);
            d1.z = pack_bf2(f[12], f[13]); d1.w = pack_bf2(f[14], f[15]);
            uint4* Kr = (uint4*)(K_b + (size_t)i * N);
            Kr[lane]      = d0;
            Kr[32 + lane] = d1;

            float acc = (((f[0]+f[1])+(f[2]+f[3])) + ((f[4]+f[5])+(f[6]+f[7])))
                      + (((f[8]+f[9])+(f[10]+f[11])) + ((f[12]+f[13])+(f[14]+f[15])));
            #pragma unroll
            for (int off = 16; off > 0; off >>= 1)
                acc += __shfl_xor_sync(0xffffffffu, acc, off);
            float r = __frcp_rn(acc);
            if (lane == 0) r_s[i] = r;
            #pragma unroll
            for (int m = 0; m < 16; m++) colacc[m] = fmaf(r, f[m], colacc[m]);
        }
        *(float4*)&part[warp][8*lane]         = make_float4(colacc[0],  colacc[1],  colacc[2],  colacc[3]);
        *(float4*)&part[warp][8*lane + 4]     = make_float4(colacc[4],  colacc[5],  colacc[6],  colacc[7]);
        *(float4*)&part[warp][256 + 8*lane]   = make_float4(colacc[8],  colacc[9],  colacc[10], colacc[11]);
        *(float4*)&part[warp][256 + 8*lane+4] = make_float4(colacc[12], colacc[13], colacc[14], colacc[15]);
        __syncthreads();
        float s = 0.f;
        #pragma unroll
        for (int w = 0; w < NWARP; w++) s += part[w][tid];
        c_s[tid] = __frcp_rn(s);
        __syncthreads();
    }

    // ================= Iterations 1..9: one pass over K each ================
    for (int t = 1; t < NITER; t++) {
        float colacc[16];
        #pragma unroll
        for (int m = 0; m < 16; m++) colacc[m] = 0.f;

        // Lane's c[j] values are loop-invariant across rows: hoist to regs.
        float4 c0 = *(const float4*)(c_s + 8 * lane);
        float4 c1 = *(const float4*)(c_s + 8 * lane + 4);
        float4 c2 = *(const float4*)(c_s + 256 + 8 * lane);
        float4 c3 = *(const float4*)(c_s + 256 + 8 * lane + 4);

        const uint4* K0 = (const uint4*)(K_b + (size_t)warp * N);
        uint4 d0 = K0[lane];
        uint4 d1 = K0[32 + lane];

        for (int ri = 0; ri < ROWS_PER_WARP; ri++) {
            uint4 cur0 = d0, cur1 = d1;
            if (ri + 1 < ROWS_PER_WARP) {   // prefetch next row
                const uint4* Kn = (const uint4*)(K_b + (size_t)(warp + (ri + 1) * NWARP) * N);
                d0 = Kn[lane];
                d1 = Kn[32 + lane];
            }
            float f[16];
            cvt8(cur0, f);
            cvt8(cur1, f + 8);

            // Row dot with 4 independent FMA chains.
            float e0 = f[0] * c0.x;  e0 = fmaf(f[1],  c0.y, e0);
            float e1 = f[2] * c0.z;  e1 = fmaf(f[3],  c0.w, e1);
            float e2 = f[4] * c1.x;  e2 = fmaf(f[5],  c1.y, e2);
            float e3 = f[6] * c1.z;  e3 = fmaf(f[7],  c1.w, e3);
            e0 = fmaf(f[8],  c2.x, e0); e1 = fmaf(f[9],  c2.y, e1);
            e2 = fmaf(f[10], c2.z, e2); e3 = fmaf(f[11], c2.w, e3);
            e0 = fmaf(f[12], c3.x, e0); e1 = fmaf(f[13], c3.y, e1);
            e2 = fmaf(f[14], c3.z, e2); e3 = fmaf(f[15], c3.w, e3);
            float acc = (e0 + e1) + (e2 + e3);
            #pragma unroll
            for (int off = 16; off > 0; off >>= 1)
                acc += __shfl_xor_sync(0xffffffffu, acc, off);
            float r = __frcp_rn(acc);
            if (lane == 0) r_s[warp + ri * NWARP] = r;
            #pragma unroll
            for (int m = 0; m < 16; m++) colacc[m] = fmaf(r, f[m], colacc[m]);
        }
        *(float4*)&part[warp][8*lane]         = make_float4(colacc[0],  colacc[1],  colacc[2],  colacc[3]);
        *(float4*)&part[warp][8*lane + 4]     = make_float4(colacc[4],  colacc[5],  colacc[6],  colacc[7]);
        *(float4*)&part[warp][256 + 8*lane]   = make_float4(colacc[8],  colacc[9],  colacc[10], colacc[11]);
        *(float4*)&part[warp][256 + 8*lane+4] = make_float4(colacc[12], colacc[13], colacc[14], colacc[15]);
        __syncthreads();
        float s = 0.f;
        #pragma unroll
        for (int w = 0; w < NWARP; w++) s += part[w][tid];
        c_s[tid] = __frcp_rn(s);
        __syncthreads();
    }

    // ================= Output: out = exp(la) * r_i * c_j (fp32 path) ========
    const float4* la4  = (const float4*)la_b;
    float4*       out4 = (float4*)(out + base);
    #pragma unroll 8
    for (int idx = tid; idx < (N * N) / 4; idx += TPB) {
        float4 v = la4[idx];
        int i = idx >> 7;               // (idx*4) / 512
        int j = (idx * 4) & (N - 1);
        float  ri = r_s[i];
        float4 cj = *(const float4*)(c_s + j);
        float4 o;
        o.x = __expf(v.x) * ri * cj.x;
        o.y = __expf(v.y) * ri * cj.y;
        o.z = __expf(v.z) * ri * cj.z;
        o.w = __expf(v.w) * ri * cj.w;
        out4[idx] = o;
    }
}

extern "C" void kernel_launch(void* const* d_in, const int* in_sizes, int n_in,
                              void* d_out, int out_size) {
    const float* la  = (const float*)d_in[0];
    float*       out = (float*)d_out;
    cudaFuncSetAttribute(sinkhorn_kernel,
                         cudaFuncAttributeMaxDynamicSharedMemorySize, DYN_SMEM);
    sinkhorn_kernel<<<BATCH, TPB, DYN_SMEM>>>(la, out);
}

// round 11
// speedup vs baseline: 1.6282x; 1.0282x over previous
#include <cuda_runtime.h>
#include <cuda_bf16.h>

// Sinkhorn over [256, 512, 512], 10 iterations, T=1.
//
// Identity: the log-space Sinkhorn iterate is always la0[i,j] + u_i + v_j, so
// the recursion collapses to diagonal scaling on K = exp(la0):
//     r = 1/(K c),  c = 1/(K^T r)   (10 times, c starts at 1)
//     out[i,j] = exp(la0[i,j]) * r_i * c_j
//
// ONE pass over K per iteration: warp-per-row computes the row dot -> r_i
// (butterfly reduce, all lanes get it), then immediately accumulates
// r_i*K[i,j] into per-lane column accumulators. Iteration 0 is fused with
// K construction (c == 1). This version adds: depth-2 K prefetch (covers the
// ~250-cycle L2 latency) and packed fma.rn.f32x2 arithmetic for the dot and
// column accumulation (halves FMA issue slots). K lives in bf16 scratch; the
// output path uses the original fp32 la.

#define BATCH 256
#define N     512
#define NITER 10
#define TPB   512
#define NWARP (TPB / 32)
#define ROWS_PER_WARP (N / NWARP)      // 32
#define DYN_SMEM (92 * 1024)           // occupancy limiter: 1 CTA/SM (L2-resident K)

// 128 MB bf16 scratch for K (static __device__ array: no runtime allocation).
__device__ __nv_bfloat16 g_K[(size_t)BATCH * N * N];

// bf16x2 packed in a u32 -> two fp32, one ALU op each.
__device__ __forceinline__ float bf_lo(unsigned v) { return __uint_as_float(v << 16); }
__device__ __forceinline__ float bf_hi(unsigned v) { return __uint_as_float(v & 0xffff0000u); }

__device__ __forceinline__ unsigned pack_bf2(float lo, float hi) {
    __nv_bfloat162 p = __floats2bfloat162_rn(lo, hi);
    return *reinterpret_cast<unsigned*>(&p);
}

// ---- f32x2 packed helpers ----
// bf16x2 u32 -> f32x2 u64: lo = v<<16, hi = v&0xffff0000, packed {lo,hi}.
__device__ __forceinline__ unsigned long long pk2(unsigned v) {
    unsigned lo = v << 16, hi = v & 0xffff0000u;
    unsigned long long p;
    asm("mov.b64 %0, {%1, %2};" : "=l"(p) : "r"(lo), "r"(hi));
    return p;
}
__device__ __forceinline__ unsigned long long fma2(unsigned long long a,
                                                   unsigned long long b,
                                                   unsigned long long c) {
    unsigned long long d;
    asm("fma.rn.f32x2 %0, %1, %2, %3;" : "=l"(d) : "l"(a), "l"(b), "l"(c));
    return d;
}
__device__ __forceinline__ float2 unpk2(unsigned long long p) {
    unsigned a, b;
    asm("mov.b64 {%0, %1}, %2;" : "=r"(a), "=r"(b) : "l"(p));
    return make_float2(__uint_as_float(a), __uint_as_float(b));
}
__device__ __forceinline__ void pack8(uint4 d0, uint4 d1, unsigned long long* k2) {
    k2[0] = pk2(d0.x); k2[1] = pk2(d0.y); k2[2] = pk2(d0.z); k2[3] = pk2(d0.w);
    k2[4] = pk2(d1.x); k2[5] = pk2(d1.y); k2[6] = pk2(d1.z); k2[7] = pk2(d1.w);
}

// One row: dot(k, c) -> butterfly reduce -> r -> r_s[i]; colacc += r * k.
__device__ __forceinline__ void proc_row(const unsigned long long* k2,
                                         const unsigned long long* cp,
                                         unsigned long long* colacc2,
                                         float* r_s, int i, int lane) {
    unsigned long long a0 = 0ull, a1 = 0ull;
    #pragma unroll
    for (int m = 0; m < 8; m += 2) {
        a0 = fma2(k2[m],     cp[m],     a0);
        a1 = fma2(k2[m + 1], cp[m + 1], a1);
    }
    float2 s0 = unpk2(a0), s1 = unpk2(a1);
    float acc = (s0.x + s0.y) + (s1.x + s1.y);
    #pragma unroll
    for (int off = 16; off > 0; off >>= 1)
        acc += __shfl_xor_sync(0xffffffffu, acc, off);
    float r = __frcp_rn(acc);
    if (lane == 0) r_s[i] = r;
    unsigned long long r2;
    unsigned ru = __float_as_uint(r);
    asm("mov.b64 %0, {%1, %1};" : "=l"(r2) : "r"(ru));
    #pragma unroll
    for (int m = 0; m < 8; m++) colacc2[m] = fma2(k2[m], r2, colacc2[m]);
}

__global__ __launch_bounds__(TPB, 1)
void sinkhorn_kernel(const float* __restrict__ la, float* __restrict__ out) {
    __shared__ float r_s[N];
    __shared__ float c_s[N];
    __shared__ float part[NWARP][N];   // per-warp column partials (32 KB)

    const int tid  = threadIdx.x;
    const int warp = tid >> 5;
    const int lane = tid & 31;
    const size_t base = (size_t)blockIdx.x * (size_t)(N * N);

    const float*   la_b = la + base;
    __nv_bfloat16* K_b  = g_K + base;

    // ================= Iteration 0, fused with K construction (c == 1) ======
    {
        float colacc[16];
        #pragma unroll
        for (int m = 0; m < 16; m++) colacc[m] = 0.f;

        for (int ri = 0; ri < ROWS_PER_WARP; ri++) {
            const int i = warp + ri * NWARP;
            const float4* lar = (const float4*)(la_b + (size_t)i * N);
            // lane's columns: j = 8*lane..8*lane+7  and  256+8*lane..+7
            float4 a0 = lar[2 * lane];
            float4 a1 = lar[2 * lane + 1];
            float4 b0 = lar[64 + 2 * lane];
            float4 b1 = lar[64 + 2 * lane + 1];
            float f[16];
            f[0]  = __expf(a0.x); f[1]  = __expf(a0.y);
            f[2]  = __expf(a0.z); f[3]  = __expf(a0.w);
            f[4]  = __expf(a1.x); f[5]  = __expf(a1.y);
            f[6]  = __expf(a1.z); f[7]  = __expf(a1.w);
            f[8]  = __expf(b0.x); f[9]  = __expf(b0.y);
            f[10] = __expf(b0.z); f[11] = __expf(b0.w);
            f[12] = __expf(b1.x); f[13] = __expf(b1.y);
            f[14] = __expf(b1.z); f[15] = __expf(b1.w);

            uint4 d0, d1;
            d0.x = pack_bf2(f[0],  f[1]);  d0.y = pack_bf2(f[2],  f[3]);
            d0.z = pack_bf2(f[4],  f[5]);  d0.w = pack_bf2(f[6],  f[7]);
            d1.x = pack_bf2(f[8],  f[9]);  d1.y = pack_bf2(f[10], f[11]);
            d1.z = pack_bf2(f[12], f[13]); d1.w = pack_bf2(f[14], f[15]);
            uint4* Kr = (uint4*)(K_b + (size_t)i * N);
            Kr[lane]      = d0;
            Kr[32 + lane] = d1;

            float acc = (((f[0]+f[1])+(f[2]+f[3])) + ((f[4]+f[5])+(f[6]+f[7])))
                      + (((f[8]+f[9])+(f[10]+f[11])) + ((f[12]+f[13])+(f[14]+f[15])));
            #pragma unroll
            for (int off = 16; off > 0; off >>= 1)
                acc += __shfl_xor_sync(0xffffffffu, acc, off);
            float r = __frcp_rn(acc);
            if (lane == 0) r_s[i] = r;
            #pragma unroll
            for (int m = 0; m < 16; m++) colacc[m] = fmaf(r, f[m], colacc[m]);
        }
        *(float4*)&part[warp][8*lane]         = make_float4(colacc[0],  colacc[1],  colacc[2],  colacc[3]);
        *(float4*)&part[warp][8*lane + 4]     = make_float4(colacc[4],  colacc[5],  colacc[6],  colacc[7]);
        *(float4*)&part[warp][256 + 8*lane]   = make_float4(colacc[8],  colacc[9],  colacc[10], colacc[11]);
        *(float4*)&part[warp][256 + 8*lane+4] = make_float4(colacc[12], colacc[13], colacc[14], colacc[15]);
        __syncthreads();
        float s = 0.f;
        #pragma unroll
        for (int w = 0; w < NWARP; w++) s += part[w][tid];
        c_s[tid] = __frcp_rn(s);
        __syncthreads();
    }

    // ===== Iterations 1..9: one pass over K each, depth-2 prefetch, f32x2 ====
    for (int t = 1; t < NITER; t++) {
        unsigned long long colacc2[8];
        #pragma unroll
        for (int m = 0; m < 8; m++) colacc2[m] = 0ull;

        // Lane's c pairs (adjacent fp32 in smem -> direct 64-bit loads).
        unsigned long long cp[8];
        #pragma unroll
        for (int m = 0; m < 4; m++) {
            cp[m]     = *(const unsigned long long*)(c_s + 8 * lane + 2 * m);
            cp[4 + m] = *(const unsigned long long*)(c_s + 256 + 8 * lane + 2 * m);
        }

        // Two rows in flight: A holds even rows, B holds odd rows.
        uint4 A0, A1, B0, B1;
        {
            const uint4* P0 = (const uint4*)(K_b + (size_t)warp * N);
            A0 = P0[lane]; A1 = P0[32 + lane];
            const uint4* P1 = (const uint4*)(K_b + (size_t)(warp + NWARP) * N);
            B0 = P1[lane]; B1 = P1[32 + lane];
        }

        for (int ri = 0; ri < ROWS_PER_WARP; ri += 2) {
            // Row ri (buffer A): pack first, then refill A for row ri+2.
            unsigned long long k2a[8];
            pack8(A0, A1, k2a);
            {
                int nr = (ri + 2 < ROWS_PER_WARP) ? ri + 2 : ROWS_PER_WARP - 1;
                const uint4* P = (const uint4*)(K_b + (size_t)(warp + nr * NWARP) * N);
                A0 = P[lane]; A1 = P[32 + lane];
            }
            proc_row(k2a, cp, colacc2, r_s, warp + ri * NWARP, lane);

            // Row ri+1 (buffer B): pack, refill B for row ri+3.
            unsigned long long k2b[8];
            pack8(B0, B1, k2b);
            {
                int nr = (ri + 3 < ROWS_PER_WARP) ? ri + 3 : ROWS_PER_WARP - 1;
                const uint4* P = (const uint4*)(K_b + (size_t)(warp + nr * NWARP) * N);
                B0 = P[lane]; B1 = P[32 + lane];
            }
            proc_row(k2b, cp, colacc2, r_s, warp + (ri + 1) * NWARP, lane);
        }

        {
            float2 t0 = unpk2(colacc2[0]), t1 = unpk2(colacc2[1]);
            float2 t2 = unpk2(colacc2[2]), t3 = unpk2(colacc2[3]);
            float2 t4 = unpk2(colacc2[4]), t5 = unpk2(colacc2[5]);
            float2 t6 = unpk2(colacc2[6]), t7 = unpk2(colacc2[7]);
            *(float4*)&part[warp][8*lane]         = make_float4(t0.x, t0.y, t1.x, t1.y);
            *(float4*)&part[warp][8*lane + 4]     = make_float4(t2.x, t2.y, t3.x, t3.y);
            *(float4*)&part[warp][256 + 8*lane]   = make_float4(t4.x, t4.y, t5.x, t5.y);
            *(float4*)&part[warp][256 + 8*lane+4] = make_float4(t6.x, t6.y, t7.x, t7.y);
        }
        __syncthreads();
        float s = 0.f;
        #pragma unroll
        for (int w = 0; w < NWARP; w++) s += part[w][tid];
        c_s[tid] = __frcp_rn(s);
        __syncthreads();
    }

    // ================= Output: out = exp(la) * r_i * c_j (fp32 path) ========
    const float4* la4  = (const float4*)la_b;
    float4*       out4 = (float4*)(out + base);
    #pragma unroll 8
    for (int idx = tid; idx < (N * N) / 4; idx += TPB) {
        float4 v = la4[idx];
        int i = idx >> 7;               // (idx*4) / 512
        int j = (idx * 4) & (N - 1);
        float  ri = r_s[i];
        float4 cj = *(const float4*)(c_s + j);
        float4 o;
        o.x = __expf(v.x) * ri * cj.x;
        o.y = __expf(v.y) * ri * cj.y;
        o.z = __expf(v.z) * ri * cj.z;
        o.w = __expf(v.w) * ri * cj.w;
        out4[idx] = o;
    }
}

extern "C" void kernel_launch(void* const* d_in, const int* in_sizes, int n_in,
                              void* d_out, int out_size) {
    const float* la  = (const float*)d_in[0];
    float*       out = (float*)d_out;
    cudaFuncSetAttribute(sinkhorn_kernel,
                         cudaFuncAttributeMaxDynamicSharedMemorySize, DYN_SMEM);
    sinkhorn_kernel<<<BATCH, TPB, DYN_SMEM>>>(la, out);
}